// round 15
// baseline (speedup 1.0000x reference)
#include <cuda_runtime.h>
#include <cuda_fp16.h>
#include <stdint.h>

#define N_NODES 100000
#define N_EDGES 1600000
#define HID 128
#define OUTD 64

#define NB_BUILD 196
#define NB_PROP  888
#define PROP_THREADS (NB_PROP * 256)      // 227328
#define BUILD_THREADS (NB_BUILD * 1024)   // 200704

// ---------------- static device scratch (no allocations allowed) ----------
__device__ __align__(16) int g_deg[N_NODES];
__device__ float g_dinv[N_NODES + 1];     // +1: pad col reads dinv[N]=0
__device__ float g_rdinv[N_NODES];
__device__ int   g_ptr[N_NODES + 1];
__device__ int   g_fill[N_NODES];
__device__ int   g_is64;
__device__ __align__(16) int g_ecol[N_EDGES];              // 4-byte edges
// z-state fp16; row = 128 B. Row N_NODES = always-zero pad row.
__device__ __align__(16) __half g_y0[(N_NODES + 1) * OUTD];
__device__ __align__(16) __half g_z1[(N_NODES + 1) * OUTD];
__device__ __align__(16) __half g_z2[(N_NODES + 1) * OUTD];

// ---------------- software grid barrier (self-resetting, replay-safe) -----
__device__ unsigned g_count;              // static zero-init; returns to 0
__device__ volatile unsigned g_gen;       // monotonic generation

__device__ __forceinline__ void grid_barrier(unsigned nb) {
    __syncthreads();
    if (threadIdx.x == 0) {
        __threadfence();                   // publish this block's writes
        unsigned snap = g_gen;
        unsigned old = atomicAdd(&g_count, 1);
        if (old == nb - 1) {
            g_count = 0;                   // reset for next use/replay
            __threadfence();
            g_gen = snap + 1;              // release
        } else {
            while (g_gen == snap) __nanosleep(64);
        }
    }
    __syncthreads();
    __threadfence();
}

// ---------------- buildA: zero deg + dtype probe -> barrier -> hist -------
__global__ void __launch_bounds__(1024, 2) k_buildA(const void* __restrict__ eiv) {
    const int t = threadIdx.x;
    const int gid = blockIdx.x * 1024 + t;

    for (int i = gid; i < N_NODES; i += BUILD_THREADS) g_deg[i] = 0;

    if (blockIdx.x == 0) {
        __shared__ int big;
        if (t == 0) big = 0;
        __syncthreads();
        const unsigned long long* p = (const unsigned long long*)eiv;
        for (int k = t; k < 2048; k += 1024)
            if (p[k] >= (unsigned long long)N_NODES) big = 1;
        __syncthreads();
        if (t == 0) g_is64 = big ? 0 : 1;
    }

    grid_barrier(NB_BUILD);

    const int is64 = g_is64;
    for (long long e = (long long)gid * 2; e < N_EDGES; e += (long long)BUILD_THREADS * 2) {
        int r0, r1;
        if (is64) {
            longlong2 rr = __ldg((const longlong2*)((const long long*)eiv + e));
            r0 = (int)rr.x; r1 = (int)rr.y;
        } else {
            int2 rr = __ldg((const int2*)((const int*)eiv + e));
            r0 = rr.x; r1 = rr.y;
        }
        if (r0 >= 0 && r0 < N_NODES) atomicAdd(&g_deg[r0], 1);
        if (e + 1 < N_EDGES && r1 >= 0 && r1 < N_NODES) atomicAdd(&g_deg[r1], 1);
    }
}

// ---------------- buildB: scan (self-offset) -> barrier -> scatter --------
#define NODE_CHUNK 512
__global__ void __launch_bounds__(1024, 2) k_buildB(const void* __restrict__ eiv) {
    __shared__ int red[32];
    __shared__ int ws[16];
    __shared__ int s_boff;
    const int t = threadIdx.x;
    const int b = blockIdx.x;
    const int limit = b * NODE_CHUNK;     // multiple of 4 -> int4 aligned

    // block offset = sum deg[0 .. limit)
    int o = 0;
    for (int i = t * 4; i < limit; i += 4096) {
        int4 d = *(const int4*)(g_deg + i);
        o += d.x + d.y + d.z + d.w;
    }
    #pragma unroll
    for (int s = 16; s > 0; s >>= 1) o += __shfl_down_sync(0xffffffffu, o, s);
    if ((t & 31) == 0) red[t >> 5] = o;
    __syncthreads();
    if (t < 32) {
        int v = red[t];
        #pragma unroll
        for (int s = 16; s > 0; s >>= 1) v += __shfl_down_sync(0xffffffffu, v, s);
        if (t == 0) s_boff = v;
    }
    __syncthreads();
    const int boff = s_boff;

    // local scan of NODE_CHUNK degrees (threads 0..511)
    int d = 0, incl = 0;
    int i = limit + t;
    if (t < NODE_CHUNK) {
        d = (i < N_NODES) ? g_deg[i] : 0;
        incl = d;
        int lane = t & 31;
        #pragma unroll
        for (int s = 1; s < 32; s <<= 1) {
            int u = __shfl_up_sync(0xffffffffu, incl, s);
            if (lane >= s) incl += u;
        }
        if (lane == 31) ws[t >> 5] = incl;
    }
    __syncthreads();
    if (t < 16) {
        int v = ws[t];
        #pragma unroll
        for (int s = 1; s < 16; s <<= 1) {
            int u = __shfl_up_sync(0x0000ffffu, v, s);
            if (t >= s) v += u;
        }
        ws[t] = v;
    }
    __syncthreads();
    if (t < NODE_CHUNK && i < N_NODES) {
        int wbase = (t >= 32) ? ws[(t >> 5) - 1] : 0;
        int excl = boff + wbase + incl - d;
        g_ptr[i]  = excl;
        g_fill[i] = excl;
        float df = (float)(d < 1 ? 1 : d);
        g_dinv[i]  = rsqrtf(df);
        g_rdinv[i] = sqrtf(df);
    }
    if (b == NB_BUILD - 1 && t == 0)
        g_ptr[N_NODES] = boff + ws[15];

    grid_barrier(NB_BUILD);

    // scatter (unweighted cols, 2 edges per iteration)
    const int is64 = g_is64;
    const int gid = b * 1024 + t;
    for (long long e = (long long)gid * 2; e < N_EDGES; e += (long long)BUILD_THREADS * 2) {
        int r0, r1, c0, c1;
        if (is64) {
            longlong2 rr = __ldg((const longlong2*)((const long long*)eiv + e));
            longlong2 cc = __ldg((const longlong2*)((const long long*)eiv + N_EDGES + e));
            r0 = (int)rr.x; r1 = (int)rr.y; c0 = (int)cc.x; c1 = (int)cc.y;
        } else {
            int2 rr = __ldg((const int2*)((const int*)eiv + e));
            int2 cc = __ldg((const int2*)((const int*)eiv + N_EDGES + e));
            r0 = rr.x; r1 = rr.y; c0 = cc.x; c1 = cc.y;
        }
        if (r0 >= 0 && r0 < N_NODES && c0 >= 0 && c0 < N_NODES) {
            int slot = atomicAdd(&g_fill[r0], 1);
            g_ecol[slot] = c0;
        }
        if (e + 1 < N_EDGES && r1 >= 0 && r1 < N_NODES && c1 >= 0 && c1 < N_NODES) {
            int slot = atomicAdd(&g_fill[r1], 1);
            g_ecol[slot] = c1;
        }
    }
}

// ---------------- y0 = x @ W^T (shared-staged x tile, fp16 out) -----------
#define GTILE 16
#define XROW 136
__global__ void __launch_bounds__(128) k_gemm(const float* __restrict__ x,
                                              const float* __restrict__ W) {
    __shared__ float sx[GTILE * XROW];

    const int tid   = threadIdx.x;
    const int warp  = tid >> 5;
    const int lane  = tid & 31;
    const int o     = warp * 16 + (lane & 15);
    const int khalf = lane >> 4;

    float4 wr[16];
    const float4* Wv = (const float4*)(W + o * HID + khalf * 64);
#pragma unroll
    for (int i = 0; i < 16; i++) wr[i] = Wv[i];

    const int base = blockIdx.x * GTILE;
    const float4* xg = (const float4*)(x + (long long)base * HID);
#pragma unroll
    for (int j = 0; j < 4; j++) {
        int f4 = tid + j * 128;
        int t  = f4 >> 5;
        int k  = f4 & 31;
        float4 v = xg[f4];
        int word = t * XROW + ((k < 16) ? (k * 4) : (68 + (k - 16) * 4));
        *(float4*)(sx + word) = v;
    }
    __syncthreads();

#pragma unroll 1
    for (int t = 0; t < GTILE; t++) {
        const float4* xv = (const float4*)(sx + t * XROW + khalf * 68);
        float ax = 0.f, ay = 0.f, az = 0.f, aw = 0.f;
#pragma unroll
        for (int i = 0; i < 16; i++) {
            float4 xi = xv[i];
            ax += xi.x * wr[i].x;
            ay += xi.y * wr[i].y;
            az += xi.z * wr[i].z;
            aw += xi.w * wr[i].w;
        }
        float s = (ax + ay) + (az + aw);
        s += __shfl_down_sync(0xffffffffu, s, 16);
        if (khalf == 0) g_y0[(base + t) * OUTD + o] = __float2half_rn(s);
    }
}

// ---------------- propagate cores (R14 structure, 4-deep pipeline) --------
#define PADC N_NODES

__device__ __forceinline__ void acc4(uint2 u, float w,
                                     float& ax, float& ay, float& az, float& aw) {
    float2 f0 = __half22float2(*(const __half2*)&u.x);
    float2 f1 = __half22float2(*(const __half2*)&u.y);
    ax = fmaf(w, f0.x, ax); ay = fmaf(w, f0.y, ay);
    az = fmaf(w, f1.x, az); aw = fmaf(w, f1.y, aw);
}

__device__ __forceinline__ void prop_w(const __half* __restrict__ src,
                                       int beg, int end, int l,
                                       float& ax, float& ay,
                                       float& az, float& aw) {
    int n = end - beg;
    if (n <= 0) return;
    const uint2* __restrict__ sv = (const uint2*)src;
    int c0, c1, c2, c3;
    c0 = __ldg(&g_ecol[beg]);
    c1 = (beg + 1 < end) ? __ldg(&g_ecol[beg + 1]) : PADC;
    c2 = (beg + 2 < end) ? __ldg(&g_ecol[beg + 2]) : PADC;
    c3 = (beg + 3 < end) ? __ldg(&g_ecol[beg + 3]) : PADC;
    int e = beg + 4;
    int nb = (n + 3) >> 2;
#pragma unroll 1
    for (int b = 0; b < nb; b++) {
        uint2 u0 = __ldg(&sv[(unsigned)c0 * 16u + l]);
        uint2 u1 = __ldg(&sv[(unsigned)c1 * 16u + l]);
        uint2 u2 = __ldg(&sv[(unsigned)c2 * 16u + l]);
        uint2 u3 = __ldg(&sv[(unsigned)c3 * 16u + l]);
        float w0 = __ldg(&g_dinv[c0]);
        float w1 = __ldg(&g_dinv[c1]);
        float w2 = __ldg(&g_dinv[c2]);
        float w3 = __ldg(&g_dinv[c3]);
        int n0 = PADC, n1 = PADC, n2 = PADC, n3 = PADC;
        if (e     < end) n0 = __ldg(&g_ecol[e]);
        if (e + 1 < end) n1 = __ldg(&g_ecol[e + 1]);
        if (e + 2 < end) n2 = __ldg(&g_ecol[e + 2]);
        if (e + 3 < end) n3 = __ldg(&g_ecol[e + 3]);
        acc4(u0, w0, ax, ay, az, aw);
        acc4(u1, w1, ax, ay, az, aw);
        acc4(u2, w2, ax, ay, az, aw);
        acc4(u3, w3, ax, ay, az, aw);
        c0 = n0; c1 = n1; c2 = n2; c3 = n3;
        e += 4;
    }
}

__device__ __forceinline__ void prop_u(const __half* __restrict__ src,
                                       int beg, int end, int l,
                                       float& ax, float& ay,
                                       float& az, float& aw) {
    int n = end - beg;
    if (n <= 0) return;
    const uint2* __restrict__ sv = (const uint2*)src;
    int c0, c1, c2, c3;
    c0 = __ldg(&g_ecol[beg]);
    c1 = (beg + 1 < end) ? __ldg(&g_ecol[beg + 1]) : PADC;
    c2 = (beg + 2 < end) ? __ldg(&g_ecol[beg + 2]) : PADC;
    c3 = (beg + 3 < end) ? __ldg(&g_ecol[beg + 3]) : PADC;
    int e = beg + 4;
    int nb = (n + 3) >> 2;
#pragma unroll 1
    for (int b = 0; b < nb; b++) {
        uint2 u0 = __ldg(&sv[(unsigned)c0 * 16u + l]);
        uint2 u1 = __ldg(&sv[(unsigned)c1 * 16u + l]);
        uint2 u2 = __ldg(&sv[(unsigned)c2 * 16u + l]);
        uint2 u3 = __ldg(&sv[(unsigned)c3 * 16u + l]);
        int n0 = PADC, n1 = PADC, n2 = PADC, n3 = PADC;
        if (e     < end) n0 = __ldg(&g_ecol[e]);
        if (e + 1 < end) n1 = __ldg(&g_ecol[e + 1]);
        if (e + 2 < end) n2 = __ldg(&g_ecol[e + 2]);
        if (e + 3 < end) n3 = __ldg(&g_ecol[e + 3]);
        acc4(u0, 1.f, ax, ay, az, aw);
        acc4(u1, 1.f, ax, ay, az, aw);
        acc4(u2, 1.f, ax, ay, az, aw);
        acc4(u3, 1.f, ax, ay, az, aw);
        c0 = n0; c1 = n1; c2 = n2; c3 = n3;
        e += 4;
    }
}

__device__ __forceinline__ void store_h4(__half* dst, int idx,
                                         float ax, float ay, float az, float aw) {
    __half2 h0 = __floats2half2_rn(ax, ay);
    __half2 h1 = __floats2half2_rn(az, aw);
    uint2 o;
    o.x = *(const unsigned*)&h0;
    o.y = *(const unsigned*)&h1;
    *((uint2*)(dst) + idx) = o;
}

// --------- fused 3-layer propagate (persistent, 2 grid barriers) ----------
__global__ void __launch_bounds__(256, 6) k_prop(const float* __restrict__ bvec,
                                                 float* __restrict__ out) {
    const int tid0 = blockIdx.x * 256 + threadIdx.x;

    // layer 1: z1[v] = dinv[v]^2 * sum_c dinv[c]*y0[c]
    for (int gid = tid0; gid < N_NODES * 16; gid += PROP_THREADS) {
        int v = gid >> 4, l = gid & 15;
        float ax = 0.f, ay = 0.f, az = 0.f, aw = 0.f;
        prop_w(g_y0, g_ptr[v], g_ptr[v + 1], l, ax, ay, az, aw);
        float dv = g_dinv[v];
        float d2 = dv * dv;
        store_h4(g_z1, v * 16 + l, ax * d2, ay * d2, az * d2, aw * d2);
    }
    grid_barrier(NB_PROP);

    // layer 2: z2[v] = dinv[v]^2 * sum_c z1[c]
    for (int gid = tid0; gid < N_NODES * 16; gid += PROP_THREADS) {
        int v = gid >> 4, l = gid & 15;
        float ax = 0.f, ay = 0.f, az = 0.f, aw = 0.f;
        prop_u(g_z1, g_ptr[v], g_ptr[v + 1], l, ax, ay, az, aw);
        float dv = g_dinv[v];
        float d2 = dv * dv;
        store_h4(g_z2, v * 16 + l, ax * d2, ay * d2, az * d2, aw * d2);
    }
    grid_barrier(NB_PROP);

    // layer 3 + epilogue: out = 0.25*(y0 + rd*(z1+z2) + dv*sum z2) + b
    for (int gid = tid0; gid < N_NODES * 16; gid += PROP_THREADS) {
        int v = gid >> 4, l = gid & 15;
        float ax = 0.f, ay = 0.f, az = 0.f, aw = 0.f;
        prop_u(g_z2, g_ptr[v], g_ptr[v + 1], l, ax, ay, az, aw);
        float dv = g_dinv[v];
        float rd = g_rdinv[v];
        uint2 u0 = *((const uint2*)g_y0 + v * 16 + l);
        uint2 u1 = *((const uint2*)g_z1 + v * 16 + l);
        uint2 u2 = *((const uint2*)g_z2 + v * 16 + l);
        float2 a0  = __half22float2(*(const __half2*)&u0.x);
        float2 a0h = __half22float2(*(const __half2*)&u0.y);
        float2 a1  = __half22float2(*(const __half2*)&u1.x);
        float2 a1h = __half22float2(*(const __half2*)&u1.y);
        float2 a2  = __half22float2(*(const __half2*)&u2.x);
        float2 a2h = __half22float2(*(const __half2*)&u2.y);
        float b0 = bvec[l * 4 + 0], b1 = bvec[l * 4 + 1];
        float b2 = bvec[l * 4 + 2], b3 = bvec[l * 4 + 3];
        float4 r;
        r.x = (a0.x  + rd * (a1.x  + a2.x)  + dv * ax) * 0.25f + b0;
        r.y = (a0.y  + rd * (a1.y  + a2.y)  + dv * ay) * 0.25f + b1;
        r.z = (a0h.x + rd * (a1h.x + a2h.x) + dv * az) * 0.25f + b2;
        r.w = (a0h.y + rd * (a1h.y + a2h.y) + dv * aw) * 0.25f + b3;
        *(float4*)(out + v * OUTD + l * 4) = r;
    }
}

// ---------------- launcher ------------------------------------------------
extern "C" void kernel_launch(void* const* d_in, const int* in_sizes, int n_in,
                              void* d_out, int out_size) {
    const float* x = nullptr;
    const float* W = nullptr;
    const float* b = nullptr;
    const void*  ei = nullptr;
    for (int i = 0; i < n_in; i++) {
        long long s = in_sizes[i];
        if      (s == (long long)N_NODES * HID) x = (const float*)d_in[i];
        else if (s == (long long)OUTD * HID)    W = (const float*)d_in[i];
        else if (s == (long long)OUTD)          b = (const float*)d_in[i];
        else ei = d_in[i];
    }
    if (!x)  x  = (const float*)d_in[0];
    if (!ei) ei = d_in[1];
    if (!W)  W  = (const float*)d_in[2];
    if (!b)  b  = (const float*)d_in[3];

    float* out = (float*)d_out;

    static cudaStream_t s2 = nullptr;
    static cudaEvent_t evFork = nullptr, evJoin = nullptr;
    if (!s2) {
        cudaStreamCreateWithFlags(&s2, cudaStreamNonBlocking);
        cudaEventCreateWithFlags(&evFork, cudaEventDisableTiming);
        cudaEventCreateWithFlags(&evJoin, cudaEventDisableTiming);
    }

    cudaEventRecord(evFork, 0);
    cudaStreamWaitEvent(s2, evFork, 0);

    // main stream: fused CSR build (2 kernels, internal grid barriers)
    k_buildA<<<NB_BUILD, 1024>>>(ei);          // zero + probe | hist
    k_buildB<<<NB_BUILD, 1024>>>(ei);          // scan | scatter

    // side stream: GEMM overlaps build (builds leave >=32 free warps on most SMs)
    k_gemm<<<N_NODES / GTILE, 128, 0, s2>>>(x, W);
    cudaEventRecord(evJoin, s2);
    cudaStreamWaitEvent(0, evJoin, 0);

    // fused persistent propagate: 3 layers, 2 internal grid barriers
    k_prop<<<NB_PROP, 256>>>(b, out);
}

// round 16
// speedup vs baseline: 1.0633x; 1.0633x over previous
#include <cuda_runtime.h>
#include <cuda_fp16.h>
#include <stdint.h>

#define N_NODES 100000
#define N_EDGES 1600000
#define HID 128
#define OUTD 64

#define SCAN_B 98            // ceil(100000 / 1024)
#define N_EPAD 2000008       // padded edge capacity (1.6M + 3*100k + slack)
#define PADC   N_NODES       // sentinel col -> zero row, dinv=0
#define NB_PROP 888
#define PROP_THREADS (NB_PROP * 256)

// ---------------- static device scratch (no allocations allowed) ----------
__device__ __align__(16) int g_deg[N_NODES];
__device__ float g_dinv[N_NODES + 1];     // dinv[PADC] = 0 (static, never written)
__device__ float g_rdinv[N_NODES];
__device__ int   g_ptr[N_NODES + 1];      // PADDED spacing (multiple of 4)
__device__ int   g_fill[N_NODES];
__device__ int   g_bsum[SCAN_B];
__device__ int   g_boff[SCAN_B];
__device__ int   g_is64;
__device__ __align__(16) int g_ecol[N_EPAD];   // 4-byte cols, pre-filled PADC
// fp16 state; row = 128 B; row PADC is always-zero pad row.
__device__ __align__(16) __half g_y0[(N_NODES + 1) * OUTD];
__device__ __align__(16) __half g_z1[(N_NODES + 1) * OUTD];
__device__ __align__(16) __half g_z2[(N_NODES + 1) * OUTD];

// ---------------- software grid barrier (self-resetting, replay-safe) -----
__device__ unsigned g_count;
__device__ volatile unsigned g_gen;

__device__ __forceinline__ void grid_barrier(unsigned nb) {
    __syncthreads();
    if (threadIdx.x == 0) {
        __threadfence();
        unsigned snap = g_gen;
        unsigned old = atomicAdd(&g_count, 1);
        if (old == nb - 1) {
            g_count = 0;
            __threadfence();
            g_gen = snap + 1;
        } else {
            while (g_gen == snap) __nanosleep(64);
        }
    }
    __syncthreads();
    __threadfence();
}

// ------- init: zero deg + prefill g_ecol with PADC + dtype probe ----------
__global__ void k_init(const unsigned long long* __restrict__ p) {
    int gid = blockIdx.x * blockDim.x + threadIdx.x;
    int tot = gridDim.x * blockDim.x;
    if (gid < N_NODES) g_deg[gid] = 0;
    int4 pad4 = make_int4(PADC, PADC, PADC, PADC);
    for (int i = gid; i < N_EPAD / 4; i += tot)
        ((int4*)g_ecol)[i] = pad4;
    if (blockIdx.x == 0) {
        __shared__ int big;
        if (threadIdx.x == 0) big = 0;
        __syncthreads();
        for (int k = threadIdx.x; k < 2048; k += blockDim.x)
            if (p[k] >= (unsigned long long)N_NODES) big = 1;
        __syncthreads();
        if (threadIdx.x == 0) g_is64 = big ? 0 : 1;
    }
}

// ---------------- build: degree histogram (2 edges / thread) --------------
__global__ void k_hist(const void* __restrict__ eiv) {
    int e = (blockIdx.x * blockDim.x + threadIdx.x) * 2;
    if (e >= N_EDGES) return;
    int r0, r1;
    if (g_is64) {
        longlong2 rr = __ldg((const longlong2*)((const long long*)eiv + e));
        r0 = (int)rr.x; r1 = (int)rr.y;
    } else {
        int2 rr = __ldg((const int2*)((const int*)eiv + e));
        r0 = rr.x; r1 = rr.y;
    }
    if (r0 >= 0 && r0 < N_NODES) atomicAdd(&g_deg[r0], 1);
    if (e + 1 < N_EDGES && r1 >= 0 && r1 < N_NODES) atomicAdd(&g_deg[r1], 1);
}

#define PAD4(d) (((d) + 3) & ~3)

// ---------------- scan level 1: per-block PADDED sums ---------------------
__global__ void __launch_bounds__(1024) k_scan1() {
    __shared__ int red[32];
    int i = blockIdx.x * 1024 + threadIdx.x;
    int d = (i < N_NODES) ? g_deg[i] : 0;
    int s = PAD4(d);
    #pragma unroll
    for (int o = 16; o > 0; o >>= 1) s += __shfl_down_sync(0xffffffffu, s, o);
    if ((threadIdx.x & 31) == 0) red[threadIdx.x >> 5] = s;
    __syncthreads();
    if (threadIdx.x < 32) {
        int v = red[threadIdx.x];
        #pragma unroll
        for (int o = 16; o > 0; o >>= 1) v += __shfl_down_sync(0xffffffffu, v, o);
        if (threadIdx.x == 0) g_bsum[blockIdx.x] = v;
    }
}

// ---------------- scan level 2: exclusive scan of block sums --------------
__global__ void __launch_bounds__(128) k_scan2() {
    __shared__ int sh[128];
    int t = threadIdx.x;
    int v = (t < SCAN_B) ? g_bsum[t] : 0;
    sh[t] = v;
    __syncthreads();
    #pragma unroll
    for (int off = 1; off < 128; off <<= 1) {
        int u = (t >= off) ? sh[t - off] : 0;
        __syncthreads();
        sh[t] += u;
        __syncthreads();
    }
    if (t < SCAN_B) g_boff[t] = sh[t] - v;
    if (t == SCAN_B - 1) g_ptr[N_NODES] = sh[t];
}

// ------ scan level 3: local PADDED scan + apply -> ptr, fill, dinv --------
__global__ void __launch_bounds__(1024) k_scan3() {
    __shared__ int warp_sums[32];
    int t = threadIdx.x;
    int i = blockIdx.x * 1024 + t;
    int d = (i < N_NODES) ? g_deg[i] : 0;
    int dp = PAD4(d);
    int incl = dp;
    int lane = t & 31;
    #pragma unroll
    for (int o = 1; o < 32; o <<= 1) {
        int u = __shfl_up_sync(0xffffffffu, incl, o);
        if (lane >= o) incl += u;
    }
    if (lane == 31) warp_sums[t >> 5] = incl;
    __syncthreads();
    if (t < 32) {
        int v = warp_sums[t];
        #pragma unroll
        for (int o = 1; o < 32; o <<= 1) {
            int u = __shfl_up_sync(0xffffffffu, v, o);
            if (t >= o) v += u;
        }
        warp_sums[t] = v;
    }
    __syncthreads();
    int wbase = (t >= 32) ? warp_sums[(t >> 5) - 1] : 0;
    int excl = g_boff[blockIdx.x] + wbase + incl - dp;
    if (i < N_NODES) {
        g_ptr[i]  = excl;
        g_fill[i] = excl;
        float df = (float)(d < 1 ? 1 : d);
        g_dinv[i]  = rsqrtf(df);
        g_rdinv[i] = sqrtf(df);
    }
}

// ---------------- scatter cols into padded CSR (2 edges / thread) ---------
__global__ void k_scatter(const void* __restrict__ eiv) {
    int e = (blockIdx.x * blockDim.x + threadIdx.x) * 2;
    if (e >= N_EDGES) return;
    int r0, r1, c0, c1;
    if (g_is64) {
        longlong2 rr = __ldg((const longlong2*)((const long long*)eiv + e));
        longlong2 cc = __ldg((const longlong2*)((const long long*)eiv + N_EDGES + e));
        r0 = (int)rr.x; r1 = (int)rr.y; c0 = (int)cc.x; c1 = (int)cc.y;
    } else {
        int2 rr = __ldg((const int2*)((const int*)eiv + e));
        int2 cc = __ldg((const int2*)((const int*)eiv + N_EDGES + e));
        r0 = rr.x; r1 = rr.y; c0 = cc.x; c1 = cc.y;
    }
    if (r0 >= 0 && r0 < N_NODES && c0 >= 0 && c0 < N_NODES) {
        int slot = atomicAdd(&g_fill[r0], 1);
        g_ecol[slot] = c0;
    }
    if (e + 1 < N_EDGES && r1 >= 0 && r1 < N_NODES && c1 >= 0 && c1 < N_NODES) {
        int slot = atomicAdd(&g_fill[r1], 1);
        g_ecol[slot] = c1;
    }
}

// ---------------- y0 = x @ W^T (shared-staged x tile, fp16 out) -----------
#define GTILE 16
#define XROW 136
__global__ void __launch_bounds__(128) k_gemm(const float* __restrict__ x,
                                              const float* __restrict__ W) {
    __shared__ float sx[GTILE * XROW];

    const int tid   = threadIdx.x;
    const int warp  = tid >> 5;
    const int lane  = tid & 31;
    const int o     = warp * 16 + (lane & 15);
    const int khalf = lane >> 4;

    float4 wr[16];
    const float4* Wv = (const float4*)(W + o * HID + khalf * 64);
#pragma unroll
    for (int i = 0; i < 16; i++) wr[i] = Wv[i];

    const int base = blockIdx.x * GTILE;
    const float4* xg = (const float4*)(x + (long long)base * HID);
#pragma unroll
    for (int j = 0; j < 4; j++) {
        int f4 = tid + j * 128;
        int t  = f4 >> 5;
        int k  = f4 & 31;
        float4 v = xg[f4];
        int word = t * XROW + ((k < 16) ? (k * 4) : (68 + (k - 16) * 4));
        *(float4*)(sx + word) = v;
    }
    __syncthreads();

#pragma unroll 1
    for (int t = 0; t < GTILE; t++) {
        const float4* xv = (const float4*)(sx + t * XROW + khalf * 68);
        float ax = 0.f, ay = 0.f, az = 0.f, aw = 0.f;
#pragma unroll
        for (int i = 0; i < 16; i++) {
            float4 xi = xv[i];
            ax += xi.x * wr[i].x;
            ay += xi.y * wr[i].y;
            az += xi.z * wr[i].z;
            aw += xi.w * wr[i].w;
        }
        float s = (ax + ay) + (az + aw);
        s += __shfl_down_sync(0xffffffffu, s, 16);
        if (khalf == 0) g_y0[(base + t) * OUTD + o] = __float2half_rn(s);
    }
}

// -------- propagate cores: UNPREDICATED 4-deep pipeline (padded lists) ----
__device__ __forceinline__ void acc4(uint2 u, float w,
                                     float& ax, float& ay, float& az, float& aw) {
    float2 f0 = __half22float2(*(const __half2*)&u.x);
    float2 f1 = __half22float2(*(const __half2*)&u.y);
    ax = fmaf(w, f0.x, ax); ay = fmaf(w, f0.y, ay);
    az = fmaf(w, f1.x, az); aw = fmaf(w, f1.y, aw);
}

// weighted (layer 1): s = sum_c dinv[c]*y0[c]
__device__ __forceinline__ void prop_w(const __half* __restrict__ src,
                                       int beg, int end, int l,
                                       float& ax, float& ay,
                                       float& az, float& aw) {
    int n = end - beg;                      // multiple of 4 (padded)
    if (n <= 0) return;
    const uint2* __restrict__ sv = (const uint2*)src;
    int c0 = __ldg(&g_ecol[beg]);
    int c1 = __ldg(&g_ecol[beg + 1]);
    int c2 = __ldg(&g_ecol[beg + 2]);
    int c3 = __ldg(&g_ecol[beg + 3]);
    int e = beg + 4;
    int nb = n >> 2;
#pragma unroll 1
    for (int b = 0; b < nb; b++) {
        uint2 u0 = __ldg(&sv[(unsigned)c0 * 16u + l]);
        uint2 u1 = __ldg(&sv[(unsigned)c1 * 16u + l]);
        uint2 u2 = __ldg(&sv[(unsigned)c2 * 16u + l]);
        uint2 u3 = __ldg(&sv[(unsigned)c3 * 16u + l]);
        float w0 = __ldg(&g_dinv[c0]);
        float w1 = __ldg(&g_dinv[c1]);
        float w2 = __ldg(&g_dinv[c2]);
        float w3 = __ldg(&g_dinv[c3]);
        int n0 = __ldg(&g_ecol[e]);         // unpredicated (slack-capped array)
        int n1 = __ldg(&g_ecol[e + 1]);
        int n2 = __ldg(&g_ecol[e + 2]);
        int n3 = __ldg(&g_ecol[e + 3]);
        acc4(u0, w0, ax, ay, az, aw);
        acc4(u1, w1, ax, ay, az, aw);
        acc4(u2, w2, ax, ay, az, aw);
        acc4(u3, w3, ax, ay, az, aw);
        c0 = n0; c1 = n1; c2 = n2; c3 = n3;
        e += 4;
    }
}

// unweighted (layers 2-3): s = sum_c z[c]
__device__ __forceinline__ void prop_u(const __half* __restrict__ src,
                                       int beg, int end, int l,
                                       float& ax, float& ay,
                                       float& az, float& aw) {
    int n = end - beg;
    if (n <= 0) return;
    const uint2* __restrict__ sv = (const uint2*)src;
    int c0 = __ldg(&g_ecol[beg]);
    int c1 = __ldg(&g_ecol[beg + 1]);
    int c2 = __ldg(&g_ecol[beg + 2]);
    int c3 = __ldg(&g_ecol[beg + 3]);
    int e = beg + 4;
    int nb = n >> 2;
#pragma unroll 1
    for (int b = 0; b < nb; b++) {
        uint2 u0 = __ldg(&sv[(unsigned)c0 * 16u + l]);
        uint2 u1 = __ldg(&sv[(unsigned)c1 * 16u + l]);
        uint2 u2 = __ldg(&sv[(unsigned)c2 * 16u + l]);
        uint2 u3 = __ldg(&sv[(unsigned)c3 * 16u + l]);
        int n0 = __ldg(&g_ecol[e]);
        int n1 = __ldg(&g_ecol[e + 1]);
        int n2 = __ldg(&g_ecol[e + 2]);
        int n3 = __ldg(&g_ecol[e + 3]);
        acc4(u0, 1.f, ax, ay, az, aw);
        acc4(u1, 1.f, ax, ay, az, aw);
        acc4(u2, 1.f, ax, ay, az, aw);
        acc4(u3, 1.f, ax, ay, az, aw);
        c0 = n0; c1 = n1; c2 = n2; c3 = n3;
        e += 4;
    }
}

__device__ __forceinline__ void store_h4(__half* dst, int idx,
                                         float ax, float ay, float az, float aw) {
    __half2 h0 = __floats2half2_rn(ax, ay);
    __half2 h1 = __floats2half2_rn(az, aw);
    uint2 o;
    o.x = *(const unsigned*)&h0;
    o.y = *(const unsigned*)&h1;
    *((uint2*)(dst) + idx) = o;
}

// --------- fused 3-layer propagate (persistent, 2 grid barriers) ----------
__global__ void __launch_bounds__(256, 6) k_prop(const float* __restrict__ bvec,
                                                 float* __restrict__ out) {
    const int tid0 = blockIdx.x * 256 + threadIdx.x;

    // layer 1: z1[v] = dinv[v]^2 * sum_c dinv[c]*y0[c]
    for (int gid = tid0; gid < N_NODES * 16; gid += PROP_THREADS) {
        int v = gid >> 4, l = gid & 15;
        float ax = 0.f, ay = 0.f, az = 0.f, aw = 0.f;
        prop_w(g_y0, g_ptr[v], g_ptr[v + 1], l, ax, ay, az, aw);
        float dv = g_dinv[v];
        float d2 = dv * dv;
        store_h4(g_z1, v * 16 + l, ax * d2, ay * d2, az * d2, aw * d2);
    }
    grid_barrier(NB_PROP);

    // layer 2: z2[v] = dinv[v]^2 * sum_c z1[c]
    for (int gid = tid0; gid < N_NODES * 16; gid += PROP_THREADS) {
        int v = gid >> 4, l = gid & 15;
        float ax = 0.f, ay = 0.f, az = 0.f, aw = 0.f;
        prop_u(g_z1, g_ptr[v], g_ptr[v + 1], l, ax, ay, az, aw);
        float dv = g_dinv[v];
        float d2 = dv * dv;
        store_h4(g_z2, v * 16 + l, ax * d2, ay * d2, az * d2, aw * d2);
    }
    grid_barrier(NB_PROP);

    // layer 3 + epilogue: out = 0.25*(y0 + rd*(z1+z2) + dv*sum z2) + b
    for (int gid = tid0; gid < N_NODES * 16; gid += PROP_THREADS) {
        int v = gid >> 4, l = gid & 15;
        float ax = 0.f, ay = 0.f, az = 0.f, aw = 0.f;
        prop_u(g_z2, g_ptr[v], g_ptr[v + 1], l, ax, ay, az, aw);
        float dv = g_dinv[v];
        float rd = g_rdinv[v];
        uint2 u0 = *((const uint2*)g_y0 + v * 16 + l);
        uint2 u1 = *((const uint2*)g_z1 + v * 16 + l);
        uint2 u2 = *((const uint2*)g_z2 + v * 16 + l);
        float2 a0  = __half22float2(*(const __half2*)&u0.x);
        float2 a0h = __half22float2(*(const __half2*)&u0.y);
        float2 a1  = __half22float2(*(const __half2*)&u1.x);
        float2 a1h = __half22float2(*(const __half2*)&u1.y);
        float2 a2  = __half22float2(*(const __half2*)&u2.x);
        float2 a2h = __half22float2(*(const __half2*)&u2.y);
        float b0 = bvec[l * 4 + 0], b1 = bvec[l * 4 + 1];
        float b2 = bvec[l * 4 + 2], b3 = bvec[l * 4 + 3];
        float4 r;
        r.x = (a0.x  + rd * (a1.x  + a2.x)  + dv * ax) * 0.25f + b0;
        r.y = (a0.y  + rd * (a1.y  + a2.y)  + dv * ay) * 0.25f + b1;
        r.z = (a0h.x + rd * (a1h.x + a2h.x) + dv * az) * 0.25f + b2;
        r.w = (a0h.y + rd * (a1h.y + a2h.y) + dv * aw) * 0.25f + b3;
        *(float4*)(out + v * OUTD + l * 4) = r;
    }
}

// ---------------- launcher ------------------------------------------------
extern "C" void kernel_launch(void* const* d_in, const int* in_sizes, int n_in,
                              void* d_out, int out_size) {
    const float* x = nullptr;
    const float* W = nullptr;
    const float* b = nullptr;
    const void*  ei = nullptr;
    for (int i = 0; i < n_in; i++) {
        long long s = in_sizes[i];
        if      (s == (long long)N_NODES * HID) x = (const float*)d_in[i];
        else if (s == (long long)OUTD * HID)    W = (const float*)d_in[i];
        else if (s == (long long)OUTD)          b = (const float*)d_in[i];
        else ei = d_in[i];
    }
    if (!x)  x  = (const float*)d_in[0];
    if (!ei) ei = d_in[1];
    if (!W)  W  = (const float*)d_in[2];
    if (!b)  b  = (const float*)d_in[3];

    float* out = (float*)d_out;

    const int TB = 256;
    const int eb2 = (N_EDGES / 2 + TB - 1) / TB;  // 3125
    const int nb  = (N_NODES + TB - 1) / TB;      // 391

    static cudaStream_t s2 = nullptr;
    static cudaEvent_t evFork = nullptr, evJoin = nullptr;
    if (!s2) {
        cudaStreamCreateWithFlags(&s2, cudaStreamNonBlocking);
        cudaEventCreateWithFlags(&evFork, cudaEventDisableTiming);
        cudaEventCreateWithFlags(&evJoin, cudaEventDisableTiming);
    }

    // Fork: GEMM overlaps the CSR build (R14 arrangement — measured best).
    cudaEventRecord(evFork, 0);
    cudaStreamWaitEvent(s2, evFork, 0);
    k_gemm<<<N_NODES / GTILE, 128, 0, s2>>>(x, W);   // y0 = x @ W^T
    cudaEventRecord(evJoin, s2);

    // CSR build on the main stream (overlaps with GEMM)
    k_init<<<nb, TB>>>((const unsigned long long*)ei);  // zero+prefill+probe
    k_hist<<<eb2, TB>>>(ei);
    k_scan1<<<SCAN_B, 1024>>>();                        // padded block sums
    k_scan2<<<1, 128>>>();                              // scan of block sums
    k_scan3<<<SCAN_B, 1024>>>();                        // padded ptr+fill+dinv
    k_scatter<<<eb2, TB>>>(ei);

    cudaStreamWaitEvent(0, evJoin, 0);       // join: prop needs y0 + CSR

    // fused persistent propagate: 3 layers, 2 internal grid barriers
    k_prop<<<NB_PROP, 256>>>(b, out);
}